// round 15
// baseline (speedup 1.0000x reference)
#include <cuda_runtime.h>
#include <cuda_bf16.h>
#include <math.h>
#include <stdint.h>

#define B_ 2
#define T_ 2048
#define C_ 768
#define H_ 12
#define D_ 64
#define M_ (B_*T_)       // 4096
#define NQKV_ (3*C_)     // 2304
#define K3_ (3*C_)       // expanded K = 2304
#define KS2 64           // k-elems per GEMM slab
#define NSLAB2 (K3_/KS2) // 36

// ---------------------------------------------------------------------------
// Scratch (allocation-free rule: __device__ globals).
// Referenced ONLY from device code (host shadow-symbol bug, see R8).
// ---------------------------------------------------------------------------
__device__ __align__(256) __nv_bfloat16 g_qh[B_*H_*T_*D_], g_ql[B_*H_*T_*D_]; // [bh][t][d]
__device__ __align__(256) __nv_bfloat16 g_kh[B_*H_*T_*D_], g_kl[B_*H_*T_*D_]; // [bh][t][d]
__device__ __align__(256) __nv_bfloat16 g_vh[B_*H_*T_*D_], g_vl[B_*H_*T_*D_]; // [bh][d][t] (transposed!)
__device__ __align__(256) __nv_bfloat16 g_x2[M_*K3_];      // x expanded [M][3K]: hi|hi|lo
__device__ __align__(256) __nv_bfloat16 g_a2[M_*K3_];      // attn out expanded
__device__ __align__(256) __nv_bfloat16 g_w2q[NQKV_*K3_];  // Wqkv^T expanded [N][3K]: hi|lo|hi
__device__ __align__(256) __nv_bfloat16 g_w2o[C_*K3_];     // Wout^T expanded

__device__ __forceinline__ uint32_t pack_bf(__nv_bfloat16 a, __nv_bfloat16 b) {
    return (uint32_t)__bfloat16_as_ushort(a) | ((uint32_t)__bfloat16_as_ushort(b) << 16);
}
__device__ __forceinline__ uint32_t smem_u32(const void* p) {
    uint32_t a;
    asm("{ .reg .u64 t; cvta.to.shared.u64 t, %1; cvt.u32.u64 %0, t; }" : "=r"(a) : "l"(p));
    return a;
}
__device__ __forceinline__ void cp16(uint32_t dst, const void* src) {
    asm volatile("cp.async.cg.shared.global [%0], [%1], 16;" :: "r"(dst), "l"(src));
}
#define CP_COMMIT() asm volatile("cp.async.commit_group;")
#define CP_WAIT(n)  asm volatile("cp.async.wait_group %0;" :: "n"(n))

#define MMA_BF16(acc, a, b0, b1) asm volatile( \
    "mma.sync.aligned.m16n8k16.row.col.f32.bf16.bf16.f32 " \
    "{%0,%1,%2,%3}, {%4,%5,%6,%7}, {%8,%9}, {%0,%1,%2,%3};" \
    : "+f"((acc)[0]), "+f"((acc)[1]), "+f"((acc)[2]), "+f"((acc)[3]) \
    : "r"((a)[0]), "r"((a)[1]), "r"((a)[2]), "r"((a)[3]), "r"(b0), "r"(b1))

#define LDMX4(r, addr) asm volatile( \
    "ldmatrix.sync.aligned.m8n8.x4.shared.b16 {%0,%1,%2,%3}, [%4];" \
    : "=r"((r)[0]), "=r"((r)[1]), "=r"((r)[2]), "=r"((r)[3]) : "r"(addr))

// ---------------------------------------------------------------------------
// Prep 1: x fp32 [M][C] -> g_x2 bf16 [M][3C] = [hi | hi | lo]
// ---------------------------------------------------------------------------
__global__ void split_expand_kernel(const float* __restrict__ src, int n4) {
    int i = blockIdx.x * blockDim.x + threadIdx.x;
    if (i >= n4) return;
    float4 v = ((const float4*)src)[i];
    float vv[4] = {v.x, v.y, v.z, v.w};
    int idx = i * 4;
    int m = idx / C_, k = idx % C_;
    size_t base = (size_t)m * K3_ + k;
#pragma unroll
    for (int j = 0; j < 4; j++) {
        __nv_bfloat16 hi = __float2bfloat16(vv[j]);
        __nv_bfloat16 lo = __float2bfloat16(vv[j] - __bfloat162float(hi));
        g_x2[base + j]          = hi;
        g_x2[base + C_ + j]     = hi;
        g_x2[base + 2*C_ + j]   = lo;
    }
}

// ---------------------------------------------------------------------------
// Prep 2: W fp32 [K][N] -> Wt bf16 [N][3K] = [hi | lo | hi]
// ---------------------------------------------------------------------------
template<int WHICH>
__global__ void transpose_split_expand_kernel(const float* __restrict__ W) {
    const int K = C_;
    const int N = (WHICH == 0) ? NQKV_ : C_;
    __nv_bfloat16* Bt = (WHICH == 0) ? g_w2q : g_w2o;

    __shared__ float tile[32][33];
    const int c0 = blockIdx.x * 32;
    const int r0 = blockIdx.y * 32;
    const int tx = threadIdx.x, ty = threadIdx.y;
#pragma unroll
    for (int i = 0; i < 4; i++)
        tile[ty + i*8][tx] = W[(size_t)(r0 + ty + i*8) * N + c0 + tx];
    __syncthreads();
#pragma unroll
    for (int i = 0; i < 4; i++) {
        float v = tile[tx][ty + i*8];
        __nv_bfloat16 hi = __float2bfloat16(v);
        __nv_bfloat16 lo = __float2bfloat16(v - __bfloat162float(hi));
        int n = c0 + ty + i*8, k = r0 + tx;
        size_t base = (size_t)n * K3_;
        Bt[base + k]        = hi;
        Bt[base + K + k]    = lo;
        Bt[base + 2*K + k]  = hi;
    }
}

// ---------------------------------------------------------------------------
// HMMA GEMM: K-slab 64, THREE-stage pipeline, WAIT(1), one barrier per slab.
// Pattern: WAIT(1) [group ks done, ks+1 in flight]; sync; issue(ks+2);
//          compute(ks%3).  issue targets stage (ks-1)%3 whose readers all
//          passed this iteration's barrier.  Exactly one commit per iter.
// Pitch 144 (128B data + 16 pad) -> ldmatrix 8-row gathers conflict-free.
// smem: 3 stages x (A 128x144 + B 128x144) = 110592 B.
// ---------------------------------------------------------------------------
#define GPITCH 144
#define G_B_OFF (128*GPITCH)      // 18432
#define G_STG   (256*GPITCH)      // 36864
#define GEMM_SMEM (3*G_STG)       // 110592

template<int MODE>
__global__ __launch_bounds__(256) void mma_gemm_kernel(float* __restrict__ outp)
{
    const __nv_bfloat16* __restrict__ A2 = (MODE == 0) ? g_x2 : g_a2;
    const __nv_bfloat16* __restrict__ B2 = (MODE == 0) ? g_w2q : g_w2o;

    extern __shared__ unsigned char smem[];
    const uint32_t sbase = smem_u32(smem);

    const int tid = threadIdx.x;
    const int wid = tid >> 5, lane = tid & 31;
    const int gid = lane >> 2, tig = lane & 3;
    const int m0 = blockIdx.y << 7, n0 = blockIdx.x << 7;
    const int warp_m = wid & 1, warp_n = wid >> 1;

    float acc[4][4][4];
#pragma unroll
    for (int a = 0; a < 4; a++)
#pragma unroll
        for (int b = 0; b < 4; b++)
#pragma unroll
            for (int c = 0; c < 4; c++) acc[a][b][c] = 0.f;

    auto issue = [&](int ks) {
        const uint32_t st = sbase + (uint32_t)(ks % 3) * G_STG;
        const size_t ko = (size_t)ks * KS2;
#pragma unroll
        for (int i = 0; i < 4; i++) {
            const int c = tid + i*256;
            const int row = c >> 3, q = c & 7;
            cp16(st + row*GPITCH + q*16,           A2 + (size_t)(m0 + row)*K3_ + ko + q*8);
            cp16(st + G_B_OFF + row*GPITCH + q*16, B2 + (size_t)(n0 + row)*K3_ + ko + q*8);
        }
        CP_COMMIT();
    };

    issue(0);
    issue(1);

    const int a_mrow = warp_m*64 + (lane & 7) + ((lane >> 3) & 1)*8;
    const uint32_t a_koff = (uint32_t)(lane >> 4) * 16;
    const int b_nrow = warp_n*32 + (lane & 7) + ((lane >> 4) & 1)*8;
    const uint32_t b_koff = (uint32_t)((lane >> 3) & 1) * 16;

    for (int ks = 0; ks < NSLAB2; ks++) {
        CP_WAIT(1);          // group ks complete; group ks+1 may remain in flight
        __syncthreads();     // visible; all warps done with stage (ks-1)
        if (ks + 2 < NSLAB2) issue(ks + 2);   // overlaps compute below
        else                 CP_COMMIT();      // constant group count

        const uint32_t bufA = sbase + (uint32_t)(ks % 3) * G_STG;
        const uint32_t bufB = bufA + G_B_OFF;

#pragma unroll
        for (int kst = 0; kst < 4; kst++) {
            uint32_t af[4][4];
#pragma unroll
            for (int tm = 0; tm < 4; tm++)
                LDMX4(af[tm], bufA + (a_mrow + tm*16)*GPITCH + kst*32 + a_koff);
            uint32_t bfr[2][4];
#pragma unroll
            for (int tp = 0; tp < 2; tp++)
                LDMX4(bfr[tp], bufB + (b_nrow + tp*16)*GPITCH + kst*32 + b_koff);
#pragma unroll
            for (int tm = 0; tm < 4; tm++)
#pragma unroll
                for (int tn = 0; tn < 4; tn++)
                    MMA_BF16(acc[tm][tn], af[tm],
                             bfr[tn>>1][(tn&1)*2], bfr[tn>>1][(tn&1)*2 + 1]);
        }
    }

    // ---- epilogue ----
#pragma unroll
    for (int tm = 0; tm < 4; tm++) {
        const int r0_ = m0 + warp_m*64 + tm*16 + gid;
#pragma unroll
        for (int tn = 0; tn < 4; tn++) {
            const int col = n0 + warp_n*32 + tn*8 + tig*2;
            if (MODE == 1) {
                float2 v0 = {acc[tm][tn][0], acc[tm][tn][1]};
                float2 v1 = {acc[tm][tn][2], acc[tm][tn][3]};
                *(float2*)&outp[(size_t)r0_ * C_ + col]       = v0;
                *(float2*)&outp[(size_t)(r0_ + 8) * C_ + col] = v1;
            } else {
                const int seg = n0 / C_;
                const int nrel = col - seg * C_;
                const int hh = nrel >> 6, dd = nrel & 63;
#pragma unroll
                for (int half = 0; half < 2; half++) {
                    const int m = r0_ + half * 8;
                    const int bb = m >> 11, tt = m & (T_ - 1);
                    const int bhh = bb*H_ + hh;
                    float v0 = acc[tm][tn][half*2], v1 = acc[tm][tn][half*2 + 1];
                    __nv_bfloat16 h0 = __float2bfloat16(v0);
                    __nv_bfloat16 h1 = __float2bfloat16(v1);
                    __nv_bfloat16 l0 = __float2bfloat16(v0 - __bfloat162float(h0));
                    __nv_bfloat16 l1 = __float2bfloat16(v1 - __bfloat162float(h1));
                    if (seg == 0) {
                        size_t base = ((size_t)bhh*T_ + tt)*D_ + dd;
                        *(uint32_t*)&g_qh[base] = pack_bf(h0, h1);
                        *(uint32_t*)&g_ql[base] = pack_bf(l0, l1);
                    } else if (seg == 1) {
                        size_t base = ((size_t)bhh*T_ + tt)*D_ + dd;
                        *(uint32_t*)&g_kh[base] = pack_bf(h0, h1);
                        *(uint32_t*)&g_kl[base] = pack_bf(l0, l1);
                    } else {
                        size_t base = ((size_t)bhh*D_ + dd)*T_ + tt;  // d-major
                        g_vh[base]      = h0;  g_vl[base]      = l0;
                        g_vh[base + T_] = h1;  g_vl[base + T_] = l1;
                    }
                }
            }
        }
    }
}

// ---------------------------------------------------------------------------
// HMMA causal flash attention (R14, passed — unchanged): Q tile 128 rows,
// 8 warps, 2-stage cp.async K/V, one WAIT(0)+barrier per k-tile.
// ---------------------------------------------------------------------------
#define APITCH 144
#define AQ_LO  (128*APITCH)        // 18432
#define AKV_OFF (2*128*APITCH)     // 36864
#define AKV_STG 36864
#define ATTN_SMEM (AKV_OFF + 2*AKV_STG)   // 110592

__global__ __launch_bounds__(256) void attn_mma_kernel() {
    extern __shared__ unsigned char smem[];
    const uint32_t sbase = smem_u32(smem);
    const int tid = threadIdx.x;
    const int wid = tid >> 5, lane = tid & 31;
    const int gid = lane >> 2, tig = lane & 3;
    const int bh = blockIdx.y;
    const int b = bh / H_, h = bh % H_;
    const int qt = (int)(gridDim.x - 1) - (int)blockIdx.x;   // heavy first
    const int ktmax = 2*qt + 1;

    const size_t qkbase = (size_t)bh * T_ * D_;
    const size_t vbase  = (size_t)bh * D_ * T_;

    auto issue_kv = [&](int kt2) {
        const uint32_t st = sbase + AKV_OFF + (uint32_t)(kt2 & 1) * AKV_STG;
#pragma unroll
        for (int i = 0; i < 2; i++) {
            const int c = tid + i*256;
            const int row = c >> 3, q = c & 7;
            const size_t gk = qkbase + (size_t)(kt2*64 + row)*D_ + q*8;
            const size_t gv = vbase + (size_t)row*T_ + kt2*64 + q*8;
            cp16(st +         row*APITCH + q*16, g_kh + gk);
            cp16(st + 9216  + row*APITCH + q*16, g_kl + gk);
            cp16(st + 18432 + row*APITCH + q*16, g_vh + gv);
            cp16(st + 27648 + row*APITCH + q*16, g_vl + gv);
        }
        CP_COMMIT();
    };

#pragma unroll
    for (int i = 0; i < 4; i++) {
        const int c = tid + i*256;
        const int row = c >> 3, q = c & 7;
        const size_t g = qkbase + (size_t)(qt*128 + row)*D_ + q*8;
        *(uint4*)(smem + row*APITCH + q*16)         = *(const uint4*)(g_qh + g);
        *(uint4*)(smem + AQ_LO + row*APITCH + q*16) = *(const uint4*)(g_ql + g);
    }

    issue_kv(0);

    float m0 = -1e30f, m1 = -1e30f, l0 = 0.f, l1 = 0.f;
    float o[8][4];
#pragma unroll
    for (int d = 0; d < 8; d++)
#pragma unroll
        for (int c = 0; c < 4; c++) o[d][c] = 0.f;

    const int arow = wid*16 + gid;
    const int grow0 = qt*128 + arow;

    for (int kt = 0; kt <= ktmax; kt++) {
        CP_WAIT(0);
        __syncthreads();
        if (kt + 1 <= ktmax) issue_kv(kt + 1);

        const unsigned char* kv = smem + AKV_OFF + (size_t)(kt & 1) * AKV_STG;
        const unsigned char* KH = kv;
        const unsigned char* KL = kv + 9216;
        const unsigned char* VH = kv + 18432;
        const unsigned char* VL = kv + 27648;

        float s[8][4];
#pragma unroll
        for (int nb = 0; nb < 8; nb++)
#pragma unroll
            for (int c = 0; c < 4; c++) s[nb][c] = 0.f;

#pragma unroll
        for (int kc = 0; kc < 4; kc++) {
            uint32_t ah[4], al[4];
            {
                const unsigned char* pa = smem + arow*APITCH + kc*32 + tig*4;
                ah[0] = *(const uint32_t*)(pa);
                ah[1] = *(const uint32_t*)(pa + 8*APITCH);
                ah[2] = *(const uint32_t*)(pa + 16);
                ah[3] = *(const uint32_t*)(pa + 8*APITCH + 16);
                const unsigned char* pl = smem + AQ_LO + arow*APITCH + kc*32 + tig*4;
                al[0] = *(const uint32_t*)(pl);
                al[1] = *(const uint32_t*)(pl + 8*APITCH);
                al[2] = *(const uint32_t*)(pl + 16);
                al[3] = *(const uint32_t*)(pl + 8*APITCH + 16);
            }
#pragma unroll
            for (int nb = 0; nb < 8; nb++) {
                const int n = nb*8 + gid;
                const unsigned char* pbh = KH + n*APITCH + kc*32 + tig*4;
                const unsigned char* pbl = KL + n*APITCH + kc*32 + tig*4;
                uint32_t bh0 = *(const uint32_t*)(pbh);
                uint32_t bh1 = *(const uint32_t*)(pbh + 16);
                uint32_t bl0 = *(const uint32_t*)(pbl);
                uint32_t bl1 = *(const uint32_t*)(pbl + 16);
                MMA_BF16(s[nb], ah, bh0, bh1);
                MMA_BF16(s[nb], ah, bl0, bl1);
                MMA_BF16(s[nb], al, bh0, bh1);
            }
        }

        const float scale = 0.125f;
        if (kt >= 2*qt) {
#pragma unroll
            for (int nb = 0; nb < 8; nb++) {
                const int colb = kt*64 + nb*8 + tig*2;
                s[nb][0] = (colb     <= grow0    ) ? s[nb][0]*scale : -1e30f;
                s[nb][1] = (colb + 1 <= grow0    ) ? s[nb][1]*scale : -1e30f;
                s[nb][2] = (colb     <= grow0 + 8) ? s[nb][2]*scale : -1e30f;
                s[nb][3] = (colb + 1 <= grow0 + 8) ? s[nb][3]*scale : -1e30f;
            }
        } else {
#pragma unroll
            for (int nb = 0; nb < 8; nb++)
#pragma unroll
                for (int c = 0; c < 4; c++) s[nb][c] *= scale;
        }

        float mx0 = -1e30f, mx1 = -1e30f;
#pragma unroll
        for (int nb = 0; nb < 8; nb++) {
            mx0 = fmaxf(mx0, fmaxf(s[nb][0], s[nb][1]));
            mx1 = fmaxf(mx1, fmaxf(s[nb][2], s[nb][3]));
        }
#pragma unroll
        for (int off = 1; off <= 2; off <<= 1) {
            mx0 = fmaxf(mx0, __shfl_xor_sync(0xffffffffu, mx0, off));
            mx1 = fmaxf(mx1, __shfl_xor_sync(0xffffffffu, mx1, off));
        }
        const float mn0 = fmaxf(m0, mx0), mn1 = fmaxf(m1, mx1);
        const float cr0 = __expf(m0 - mn0), cr1 = __expf(m1 - mn1);
        float sum0 = 0.f, sum1 = 0.f;
#pragma unroll
        for (int nb = 0; nb < 8; nb++) {
            s[nb][0] = __expf(s[nb][0] - mn0);
            s[nb][1] = __expf(s[nb][1] - mn0);
            s[nb][2] = __expf(s[nb][2] - mn1);
            s[nb][3] = __expf(s[nb][3] - mn1);
            sum0 += s[nb][0] + s[nb][1];
            sum1 += s[nb][2] + s[nb][3];
        }
#pragma unroll
        for (int off = 1; off <= 2; off <<= 1) {
            sum0 += __shfl_xor_sync(0xffffffffu, sum0, off);
            sum1 += __shfl_xor_sync(0xffffffffu, sum1, off);
        }
        l0 = l0 * cr0 + sum0;  m0 = mn0;
        l1 = l1 * cr1 + sum1;  m1 = mn1;
#pragma unroll
        for (int db = 0; db < 8; db++) {
            o[db][0] *= cr0; o[db][1] *= cr0;
            o[db][2] *= cr1; o[db][3] *= cr1;
        }

        uint32_t ph[4][4], pl[4][4];
#pragma unroll
        for (int kc = 0; kc < 4; kc++) {
#pragma unroll
            for (int part = 0; part < 2; part++) {
                const int nb = 2*kc + part;
                __nv_bfloat16 h0 = __float2bfloat16(s[nb][0]);
                __nv_bfloat16 h1 = __float2bfloat16(s[nb][1]);
                __nv_bfloat16 h2 = __float2bfloat16(s[nb][2]);
                __nv_bfloat16 h3 = __float2bfloat16(s[nb][3]);
                ph[kc][0 + part*2] = pack_bf(h0, h1);
                ph[kc][1 + part*2] = pack_bf(h2, h3);
                pl[kc][0 + part*2] = pack_bf(
                    __float2bfloat16(s[nb][0] - __bfloat162float(h0)),
                    __float2bfloat16(s[nb][1] - __bfloat162float(h1)));
                pl[kc][1 + part*2] = pack_bf(
                    __float2bfloat16(s[nb][2] - __bfloat162float(h2)),
                    __float2bfloat16(s[nb][3] - __bfloat162float(h3)));
            }
        }

#pragma unroll
        for (int kc = 0; kc < 4; kc++) {
#pragma unroll
            for (int db = 0; db < 8; db++) {
                const int n = db*8 + gid;
                const unsigned char* pbh = VH + n*APITCH + kc*32 + tig*4;
                const unsigned char* pbl = VL + n*APITCH + kc*32 + tig*4;
                uint32_t bh0 = *(const uint32_t*)(pbh);
                uint32_t bh1 = *(const uint32_t*)(pbh + 16);
                uint32_t bl0 = *(const uint32_t*)(pbl);
                uint32_t bl1 = *(const uint32_t*)(pbl + 16);
                MMA_BF16(o[db], ph[kc], bh0, bh1);
                MMA_BF16(o[db], ph[kc], bl0, bl1);
                MMA_BF16(o[db], pl[kc], bh0, bh1);
            }
        }
    }

    const float i0 = 1.f / l0, i1 = 1.f / l1;
    const int gr = b*T_ + grow0;
#pragma unroll
    for (int db = 0; db < 8; db++) {
#pragma unroll
        for (int c = 0; c < 4; c++) {
            const float val = o[db][c] * ((c < 2) ? i0 : i1);
            const int row = (c < 2) ? gr : gr + 8;
            const int col = h*64 + db*8 + tig*2 + (c & 1);
            const size_t base = (size_t)row * K3_ + col;
            __nv_bfloat16 hi = __float2bfloat16(val);
            __nv_bfloat16 lo = __float2bfloat16(val - __bfloat162float(hi));
            g_a2[base]        = hi;
            g_a2[base + C_]   = hi;
            g_a2[base + 2*C_] = lo;
        }
    }
}

// ---------------------------------------------------------------------------
extern "C" void kernel_launch(void* const* d_in, const int* in_sizes, int n_in,
                              void* d_out, int out_size) {
    const float* x    = (const float*)d_in[0];
    const float* Wqkv = (const float*)d_in[1];
    const float* Wout = (const float*)d_in[2];
    float* out = (float*)d_out;

    split_expand_kernel<<<(M_*C_/4 + 255)/256, 256>>>(x, M_*C_/4);
    transpose_split_expand_kernel<0><<<dim3(NQKV_/32, C_/32), dim3(32, 8)>>>(Wqkv);
    transpose_split_expand_kernel<1><<<dim3(C_/32, C_/32), dim3(32, 8)>>>(Wout);

    // QKV projection (HMMA, K-slab 64, 3-stage WAIT(1), 1 barrier/slab)
    cudaFuncSetAttribute(mma_gemm_kernel<0>, cudaFuncAttributeMaxDynamicSharedMemorySize,
                         GEMM_SMEM);
    mma_gemm_kernel<0><<<dim3(NQKV_/128, M_/128), 256, GEMM_SMEM>>>(nullptr);

    // Flash attention on tensor cores (128-row Q tiles, 8 warps)
    cudaFuncSetAttribute(attn_mma_kernel, cudaFuncAttributeMaxDynamicSharedMemorySize,
                         ATTN_SMEM);
    attn_mma_kernel<<<dim3(T_/128, B_*H_), 256, ATTN_SMEM>>>();

    // Output projection (HMMA)
    cudaFuncSetAttribute(mma_gemm_kernel<1>, cudaFuncAttributeMaxDynamicSharedMemorySize,
                         GEMM_SMEM);
    mma_gemm_kernel<1><<<dim3(C_/128, M_/128), 256, GEMM_SMEM>>>(out);
}

// round 16
// speedup vs baseline: 1.0864x; 1.0864x over previous
#include <cuda_runtime.h>
#include <cuda_bf16.h>
#include <math.h>
#include <stdint.h>

#define B_ 2
#define T_ 2048
#define C_ 768
#define H_ 12
#define D_ 64
#define M_ (B_*T_)       // 4096
#define NQKV_ (3*C_)     // 2304
#define K3_ (3*C_)       // expanded K = 2304
#define KS2 64           // k-elems per GEMM slab
#define NSLAB2 (K3_/KS2) // 36

// ---------------------------------------------------------------------------
// Scratch (allocation-free rule: __device__ globals).
// Referenced ONLY from device code (host shadow-symbol bug, see R8).
// ---------------------------------------------------------------------------
__device__ __align__(256) __nv_bfloat16 g_qh[B_*H_*T_*D_], g_ql[B_*H_*T_*D_]; // [bh][t][d]
__device__ __align__(256) __nv_bfloat16 g_kh[B_*H_*T_*D_], g_kl[B_*H_*T_*D_]; // [bh][t][d]
__device__ __align__(256) __nv_bfloat16 g_vh[B_*H_*T_*D_], g_vl[B_*H_*T_*D_]; // [bh][d][t] (transposed!)
__device__ __align__(256) __nv_bfloat16 g_x2[M_*K3_];      // x expanded [M][3K]: hi|hi|lo
__device__ __align__(256) __nv_bfloat16 g_a2[M_*K3_];      // attn out expanded
__device__ __align__(256) __nv_bfloat16 g_w2q[NQKV_*K3_];  // Wqkv^T expanded [N][3K]: hi|lo|hi
__device__ __align__(256) __nv_bfloat16 g_w2o[C_*K3_];     // Wout^T expanded

__device__ __forceinline__ uint32_t pack_bf(__nv_bfloat16 a, __nv_bfloat16 b) {
    return (uint32_t)__bfloat16_as_ushort(a) | ((uint32_t)__bfloat16_as_ushort(b) << 16);
}
__device__ __forceinline__ uint32_t smem_u32(const void* p) {
    uint32_t a;
    asm("{ .reg .u64 t; cvta.to.shared.u64 t, %1; cvt.u32.u64 %0, t; }" : "=r"(a) : "l"(p));
    return a;
}
__device__ __forceinline__ void cp16(uint32_t dst, const void* src) {
    asm volatile("cp.async.cg.shared.global [%0], [%1], 16;" :: "r"(dst), "l"(src));
}
#define CP_COMMIT() asm volatile("cp.async.commit_group;")
#define CP_WAIT(n)  asm volatile("cp.async.wait_group %0;" :: "n"(n))

#define MMA_BF16(acc, a, b0, b1) asm volatile( \
    "mma.sync.aligned.m16n8k16.row.col.f32.bf16.bf16.f32 " \
    "{%0,%1,%2,%3}, {%4,%5,%6,%7}, {%8,%9}, {%0,%1,%2,%3};" \
    : "+f"((acc)[0]), "+f"((acc)[1]), "+f"((acc)[2]), "+f"((acc)[3]) \
    : "r"((a)[0]), "r"((a)[1]), "r"((a)[2]), "r"((a)[3]), "r"(b0), "r"(b1))

#define LDMX4(r, addr) asm volatile( \
    "ldmatrix.sync.aligned.m8n8.x4.shared.b16 {%0,%1,%2,%3}, [%4];" \
    : "=r"((r)[0]), "=r"((r)[1]), "=r"((r)[2]), "=r"((r)[3]) : "r"(addr))

// ---------------------------------------------------------------------------
// Prep 1: x fp32 [M][C] -> g_x2 bf16 [M][3C] = [hi | hi | lo]
// ---------------------------------------------------------------------------
__global__ void split_expand_kernel(const float* __restrict__ src, int n4) {
    int i = blockIdx.x * blockDim.x + threadIdx.x;
    if (i >= n4) return;
    float4 v = ((const float4*)src)[i];
    float vv[4] = {v.x, v.y, v.z, v.w};
    int idx = i * 4;
    int m = idx / C_, k = idx % C_;
    size_t base = (size_t)m * K3_ + k;
#pragma unroll
    for (int j = 0; j < 4; j++) {
        __nv_bfloat16 hi = __float2bfloat16(vv[j]);
        __nv_bfloat16 lo = __float2bfloat16(vv[j] - __bfloat162float(hi));
        g_x2[base + j]          = hi;
        g_x2[base + C_ + j]     = hi;
        g_x2[base + 2*C_ + j]   = lo;
    }
}

// ---------------------------------------------------------------------------
// Prep 2: W fp32 [K][N] -> Wt bf16 [N][3K] = [hi | lo | hi]
// ---------------------------------------------------------------------------
template<int WHICH>
__global__ void transpose_split_expand_kernel(const float* __restrict__ W) {
    const int K = C_;
    const int N = (WHICH == 0) ? NQKV_ : C_;
    __nv_bfloat16* Bt = (WHICH == 0) ? g_w2q : g_w2o;

    __shared__ float tile[32][33];
    const int c0 = blockIdx.x * 32;
    const int r0 = blockIdx.y * 32;
    const int tx = threadIdx.x, ty = threadIdx.y;
#pragma unroll
    for (int i = 0; i < 4; i++)
        tile[ty + i*8][tx] = W[(size_t)(r0 + ty + i*8) * N + c0 + tx];
    __syncthreads();
#pragma unroll
    for (int i = 0; i < 4; i++) {
        float v = tile[tx][ty + i*8];
        __nv_bfloat16 hi = __float2bfloat16(v);
        __nv_bfloat16 lo = __float2bfloat16(v - __bfloat162float(hi));
        int n = c0 + ty + i*8, k = r0 + tx;
        size_t base = (size_t)n * K3_;
        Bt[base + k]        = hi;
        Bt[base + K + k]    = lo;
        Bt[base + 2*K + k]  = hi;
    }
}

// ---------------------------------------------------------------------------
// HMMA GEMM (R14, measured best 136us): K-slab 64, 2-stage, ONE
// WAIT(0)+barrier per slab.  smem: 2 x (A 128x144 + B 128x144) = 73728 B.
// ---------------------------------------------------------------------------
#define GPITCH 144
#define G_B_OFF (128*GPITCH)      // 18432
#define G_STG   (256*GPITCH)      // 36864
#define GEMM_SMEM (2*G_STG)       // 73728

template<int MODE>
__global__ __launch_bounds__(256) void mma_gemm_kernel(float* __restrict__ outp)
{
    const __nv_bfloat16* __restrict__ A2 = (MODE == 0) ? g_x2 : g_a2;
    const __nv_bfloat16* __restrict__ B2 = (MODE == 0) ? g_w2q : g_w2o;

    extern __shared__ unsigned char smem[];
    const uint32_t sbase = smem_u32(smem);

    const int tid = threadIdx.x;
    const int wid = tid >> 5, lane = tid & 31;
    const int gid = lane >> 2, tig = lane & 3;
    const int m0 = blockIdx.y << 7, n0 = blockIdx.x << 7;
    const int warp_m = wid & 1, warp_n = wid >> 1;

    float acc[4][4][4];
#pragma unroll
    for (int a = 0; a < 4; a++)
#pragma unroll
        for (int b = 0; b < 4; b++)
#pragma unroll
            for (int c = 0; c < 4; c++) acc[a][b][c] = 0.f;

    auto issue = [&](int ks) {
        const uint32_t st = sbase + (uint32_t)(ks & 1) * G_STG;
        const size_t ko = (size_t)ks * KS2;
#pragma unroll
        for (int i = 0; i < 4; i++) {
            const int c = tid + i*256;
            const int row = c >> 3, q = c & 7;
            cp16(st + row*GPITCH + q*16,           A2 + (size_t)(m0 + row)*K3_ + ko + q*8);
            cp16(st + G_B_OFF + row*GPITCH + q*16, B2 + (size_t)(n0 + row)*K3_ + ko + q*8);
        }
        CP_COMMIT();
    };

    issue(0);

    const int a_mrow = warp_m*64 + (lane & 7) + ((lane >> 3) & 1)*8;
    const uint32_t a_koff = (uint32_t)(lane >> 4) * 16;
    const int b_nrow = warp_n*32 + (lane & 7) + ((lane >> 4) & 1)*8;
    const uint32_t b_koff = (uint32_t)((lane >> 3) & 1) * 16;

    for (int ks = 0; ks < NSLAB2; ks++) {
        CP_WAIT(0);
        __syncthreads();
        if (ks + 1 < NSLAB2) issue(ks + 1);

        const uint32_t bufA = sbase + (uint32_t)(ks & 1) * G_STG;
        const uint32_t bufB = bufA + G_B_OFF;

#pragma unroll
        for (int kst = 0; kst < 4; kst++) {
            uint32_t af[4][4];
#pragma unroll
            for (int tm = 0; tm < 4; tm++)
                LDMX4(af[tm], bufA + (a_mrow + tm*16)*GPITCH + kst*32 + a_koff);
            uint32_t bfr[2][4];
#pragma unroll
            for (int tp = 0; tp < 2; tp++)
                LDMX4(bfr[tp], bufB + (b_nrow + tp*16)*GPITCH + kst*32 + b_koff);
#pragma unroll
            for (int tm = 0; tm < 4; tm++)
#pragma unroll
                for (int tn = 0; tn < 4; tn++)
                    MMA_BF16(acc[tm][tn], af[tm],
                             bfr[tn>>1][(tn&1)*2], bfr[tn>>1][(tn&1)*2 + 1]);
        }
    }

    // ---- epilogue ----
#pragma unroll
    for (int tm = 0; tm < 4; tm++) {
        const int r0_ = m0 + warp_m*64 + tm*16 + gid;
#pragma unroll
        for (int tn = 0; tn < 4; tn++) {
            const int col = n0 + warp_n*32 + tn*8 + tig*2;
            if (MODE == 1) {
                float2 v0 = {acc[tm][tn][0], acc[tm][tn][1]};
                float2 v1 = {acc[tm][tn][2], acc[tm][tn][3]};
                *(float2*)&outp[(size_t)r0_ * C_ + col]       = v0;
                *(float2*)&outp[(size_t)(r0_ + 8) * C_ + col] = v1;
            } else {
                const int seg = n0 / C_;
                const int nrel = col - seg * C_;
                const int hh = nrel >> 6, dd = nrel & 63;
#pragma unroll
                for (int half = 0; half < 2; half++) {
                    const int m = r0_ + half * 8;
                    const int bb = m >> 11, tt = m & (T_ - 1);
                    const int bhh = bb*H_ + hh;
                    float v0 = acc[tm][tn][half*2], v1 = acc[tm][tn][half*2 + 1];
                    __nv_bfloat16 h0 = __float2bfloat16(v0);
                    __nv_bfloat16 h1 = __float2bfloat16(v1);
                    __nv_bfloat16 l0 = __float2bfloat16(v0 - __bfloat162float(h0));
                    __nv_bfloat16 l1 = __float2bfloat16(v1 - __bfloat162float(h1));
                    if (seg == 0) {
                        size_t base = ((size_t)bhh*T_ + tt)*D_ + dd;
                        *(uint32_t*)&g_qh[base] = pack_bf(h0, h1);
                        *(uint32_t*)&g_ql[base] = pack_bf(l0, l1);
                    } else if (seg == 1) {
                        size_t base = ((size_t)bhh*T_ + tt)*D_ + dd;
                        *(uint32_t*)&g_kh[base] = pack_bf(h0, h1);
                        *(uint32_t*)&g_kl[base] = pack_bf(l0, l1);
                    } else {
                        size_t base = ((size_t)bhh*D_ + dd)*T_ + tt;  // d-major
                        g_vh[base]      = h0;  g_vl[base]      = l0;
                        g_vh[base + T_] = h1;  g_vl[base + T_] = l1;
                    }
                }
            }
        }
    }
}

// ---------------------------------------------------------------------------
// HMMA causal flash attention: Q tile 128 rows, 8 warps, 2-stage cp.async
// K/V, ONE barrier per k-tile.  NEW: all Q/K/V fragment loads via ldmatrix.x4
// (GEMM-verified lane formulas) instead of scalar LDS — removes the MIO
// bottleneck.  MMA sequence / softmax / masks / epilogue unchanged from the
// R14 passing kernel.
// ---------------------------------------------------------------------------
#define APITCH 144
#define AQ_LO  (128*APITCH)        // 18432
#define AKV_OFF (2*128*APITCH)     // 36864
#define AKV_STG 36864
#define ATTN_SMEM (AKV_OFF + 2*AKV_STG)   // 110592

__global__ __launch_bounds__(256) void attn_mma_kernel() {
    extern __shared__ unsigned char smem[];
    const uint32_t sbase = smem_u32(smem);
    const int tid = threadIdx.x;
    const int wid = tid >> 5, lane = tid & 31;
    const int gid = lane >> 2, tig = lane & 3;
    const int bh = blockIdx.y;
    const int b = bh / H_, h = bh % H_;
    const int qt = (int)(gridDim.x - 1) - (int)blockIdx.x;   // heavy first
    const int ktmax = 2*qt + 1;

    const size_t qkbase = (size_t)bh * T_ * D_;
    const size_t vbase  = (size_t)bh * D_ * T_;

    auto issue_kv = [&](int kt2) {
        const uint32_t st = sbase + AKV_OFF + (uint32_t)(kt2 & 1) * AKV_STG;
#pragma unroll
        for (int i = 0; i < 2; i++) {
            const int c = tid + i*256;
            const int row = c >> 3, q = c & 7;
            const size_t gk = qkbase + (size_t)(kt2*64 + row)*D_ + q*8;
            const size_t gv = vbase + (size_t)row*T_ + kt2*64 + q*8;
            cp16(st +         row*APITCH + q*16, g_kh + gk);
            cp16(st + 9216  + row*APITCH + q*16, g_kl + gk);
            cp16(st + 18432 + row*APITCH + q*16, g_vh + gv);
            cp16(st + 27648 + row*APITCH + q*16, g_vl + gv);
        }
        CP_COMMIT();
    };

#pragma unroll
    for (int i = 0; i < 4; i++) {
        const int c = tid + i*256;
        const int row = c >> 3, q = c & 7;
        const size_t g = qkbase + (size_t)(qt*128 + row)*D_ + q*8;
        *(uint4*)(smem + row*APITCH + q*16)         = *(const uint4*)(g_qh + g);
        *(uint4*)(smem + AQ_LO + row*APITCH + q*16) = *(const uint4*)(g_ql + g);
    }

    issue_kv(0);

    float m0 = -1e30f, m1 = -1e30f, l0 = 0.f, l1 = 0.f;
    float o[8][4];
#pragma unroll
    for (int d = 0; d < 8; d++)
#pragma unroll
        for (int c = 0; c < 4; c++) o[d][c] = 0.f;

    const int arow = wid*16 + gid;          // for mask/epilogue row math
    const int grow0 = qt*128 + arow;

    // ldmatrix lane formulas (GEMM-verified)
    const int a_row  = wid*16 + (lane & 7) + ((lane >> 3) & 1)*8;  // A frags (Q, 16 rows)
    const uint32_t a_koff = (uint32_t)(lane >> 4) * 16;
    const int b_row  = (lane & 7) + ((lane >> 4) & 1)*8;           // B frags (K/V, +tp*16)
    const uint32_t b_koff = (uint32_t)((lane >> 3) & 1) * 16;

    for (int kt = 0; kt <= ktmax; kt++) {
        CP_WAIT(0);
        __syncthreads();
        if (kt + 1 <= ktmax) issue_kv(kt + 1);

        const uint32_t kv = sbase + AKV_OFF + (uint32_t)(kt & 1) * AKV_STG;
        const uint32_t KH = kv;
        const uint32_t KL = kv + 9216;
        const uint32_t VH = kv + 18432;
        const uint32_t VL = kv + 27648;

        float s[8][4];
#pragma unroll
        for (int nb = 0; nb < 8; nb++)
#pragma unroll
            for (int c = 0; c < 4; c++) s[nb][c] = 0.f;

        // ---- S = Q K^T (3-term split), ldmatrix fragment loads ----
#pragma unroll
        for (int kc = 0; kc < 4; kc++) {
            uint32_t ah[4], al[4];
            LDMX4(ah, sbase + a_row*APITCH + kc*32 + a_koff);
            LDMX4(al, sbase + AQ_LO + a_row*APITCH + kc*32 + a_koff);
#pragma unroll
            for (int tp = 0; tp < 4; tp++) {
                uint32_t kh[4], kl[4];
                LDMX4(kh, KH + (tp*16 + b_row)*APITCH + kc*32 + b_koff);
                LDMX4(kl, KL + (tp*16 + b_row)*APITCH + kc*32 + b_koff);
                MMA_BF16(s[2*tp],   ah, kh[0], kh[1]);
                MMA_BF16(s[2*tp],   ah, kl[0], kl[1]);
                MMA_BF16(s[2*tp],   al, kh[0], kh[1]);
                MMA_BF16(s[2*tp+1], ah, kh[2], kh[3]);
                MMA_BF16(s[2*tp+1], ah, kl[2], kl[3]);
                MMA_BF16(s[2*tp+1], al, kh[2], kh[3]);
            }
        }

        const float scale = 0.125f;
        if (kt >= 2*qt) {
#pragma unroll
            for (int nb = 0; nb < 8; nb++) {
                const int colb = kt*64 + nb*8 + tig*2;
                s[nb][0] = (colb     <= grow0    ) ? s[nb][0]*scale : -1e30f;
                s[nb][1] = (colb + 1 <= grow0    ) ? s[nb][1]*scale : -1e30f;
                s[nb][2] = (colb     <= grow0 + 8) ? s[nb][2]*scale : -1e30f;
                s[nb][3] = (colb + 1 <= grow0 + 8) ? s[nb][3]*scale : -1e30f;
            }
        } else {
#pragma unroll
            for (int nb = 0; nb < 8; nb++)
#pragma unroll
                for (int c = 0; c < 4; c++) s[nb][c] *= scale;
        }

        float mx0 = -1e30f, mx1 = -1e30f;
#pragma unroll
        for (int nb = 0; nb < 8; nb++) {
            mx0 = fmaxf(mx0, fmaxf(s[nb][0], s[nb][1]));
            mx1 = fmaxf(mx1, fmaxf(s[nb][2], s[nb][3]));
        }
#pragma unroll
        for (int off = 1; off <= 2; off <<= 1) {
            mx0 = fmaxf(mx0, __shfl_xor_sync(0xffffffffu, mx0, off));
            mx1 = fmaxf(mx1, __shfl_xor_sync(0xffffffffu, mx1, off));
        }
        const float mn0 = fmaxf(m0, mx0), mn1 = fmaxf(m1, mx1);
        const float cr0 = __expf(m0 - mn0), cr1 = __expf(m1 - mn1);
        float sum0 = 0.f, sum1 = 0.f;
#pragma unroll
        for (int nb = 0; nb < 8; nb++) {
            s[nb][0] = __expf(s[nb][0] - mn0);
            s[nb][1] = __expf(s[nb][1] - mn0);
            s[nb][2] = __expf(s[nb][2] - mn1);
            s[nb][3] = __expf(s[nb][3] - mn1);
            sum0 += s[nb][0] + s[nb][1];
            sum1 += s[nb][2] + s[nb][3];
        }
#pragma unroll
        for (int off = 1; off <= 2; off <<= 1) {
            sum0 += __shfl_xor_sync(0xffffffffu, sum0, off);
            sum1 += __shfl_xor_sync(0xffffffffu, sum1, off);
        }
        l0 = l0 * cr0 + sum0;  m0 = mn0;
        l1 = l1 * cr1 + sum1;  m1 = mn1;
#pragma unroll
        for (int db = 0; db < 8; db++) {
            o[db][0] *= cr0; o[db][1] *= cr0;
            o[db][2] *= cr1; o[db][3] *= cr1;
        }

        // ---- P -> A-fragments (register-only) ----
        uint32_t ph[4][4], pl[4][4];
#pragma unroll
        for (int kc = 0; kc < 4; kc++) {
#pragma unroll
            for (int part = 0; part < 2; part++) {
                const int nb = 2*kc + part;
                __nv_bfloat16 h0 = __float2bfloat16(s[nb][0]);
                __nv_bfloat16 h1 = __float2bfloat16(s[nb][1]);
                __nv_bfloat16 h2 = __float2bfloat16(s[nb][2]);
                __nv_bfloat16 h3 = __float2bfloat16(s[nb][3]);
                ph[kc][0 + part*2] = pack_bf(h0, h1);
                ph[kc][1 + part*2] = pack_bf(h2, h3);
                pl[kc][0 + part*2] = pack_bf(
                    __float2bfloat16(s[nb][0] - __bfloat162float(h0)),
                    __float2bfloat16(s[nb][1] - __bfloat162float(h1)));
                pl[kc][1 + part*2] = pack_bf(
                    __float2bfloat16(s[nb][2] - __bfloat162float(h2)),
                    __float2bfloat16(s[nb][3] - __bfloat162float(h3)));
            }
        }

        // ---- O += P V (3-term split), ldmatrix V fragment loads ----
#pragma unroll
        for (int kc = 0; kc < 4; kc++) {
#pragma unroll
            for (int tp = 0; tp < 4; tp++) {
                uint32_t vh[4], vl[4];
                LDMX4(vh, VH + (tp*16 + b_row)*APITCH + kc*32 + b_koff);
                LDMX4(vl, VL + (tp*16 + b_row)*APITCH + kc*32 + b_koff);
                MMA_BF16(o[2*tp],   ph[kc], vh[0], vh[1]);
                MMA_BF16(o[2*tp],   ph[kc], vl[0], vl[1]);
                MMA_BF16(o[2*tp],   pl[kc], vh[0], vh[1]);
                MMA_BF16(o[2*tp+1], ph[kc], vh[2], vh[3]);
                MMA_BF16(o[2*tp+1], ph[kc], vl[2], vl[3]);
                MMA_BF16(o[2*tp+1], pl[kc], vh[2], vh[3]);
            }
        }
    }

    const float i0 = 1.f / l0, i1 = 1.f / l1;
    const int gr = b*T_ + grow0;
#pragma unroll
    for (int db = 0; db < 8; db++) {
#pragma unroll
        for (int c = 0; c < 4; c++) {
            const float val = o[db][c] * ((c < 2) ? i0 : i1);
            const int row = (c < 2) ? gr : gr + 8;
            const int col = h*64 + db*8 + tig*2 + (c & 1);
            const size_t base = (size_t)row * K3_ + col;
            __nv_bfloat16 hi = __float2bfloat16(val);
            __nv_bfloat16 lo = __float2bfloat16(val - __bfloat162float(hi));
            g_a2[base]        = hi;
            g_a2[base + C_]   = hi;
            g_a2[base + 2*C_] = lo;
        }
    }
}

// ---------------------------------------------------------------------------
extern "C" void kernel_launch(void* const* d_in, const int* in_sizes, int n_in,
                              void* d_out, int out_size) {
    const float* x    = (const float*)d_in[0];
    const float* Wqkv = (const float*)d_in[1];
    const float* Wout = (const float*)d_in[2];
    float* out = (float*)d_out;

    split_expand_kernel<<<(M_*C_/4 + 255)/256, 256>>>(x, M_*C_/4);
    transpose_split_expand_kernel<0><<<dim3(NQKV_/32, C_/32), dim3(32, 8)>>>(Wqkv);
    transpose_split_expand_kernel<1><<<dim3(C_/32, C_/32), dim3(32, 8)>>>(Wout);

    // QKV projection (HMMA, K-slab 64, 2-stage — R14 measured best)
    cudaFuncSetAttribute(mma_gemm_kernel<0>, cudaFuncAttributeMaxDynamicSharedMemorySize,
                         GEMM_SMEM);
    mma_gemm_kernel<0><<<dim3(NQKV_/128, M_/128), 256, GEMM_SMEM>>>(nullptr);

    // Flash attention on tensor cores (128-row Q tiles, 8 warps, ldmatrix)
    cudaFuncSetAttribute(attn_mma_kernel, cudaFuncAttributeMaxDynamicSharedMemorySize,
                         ATTN_SMEM);
    attn_mma_kernel<<<dim3(T_/128, B_*H_), 256, ATTN_SMEM>>>();

    // Output projection (HMMA)
    cudaFuncSetAttribute(mma_gemm_kernel<1>, cudaFuncAttributeMaxDynamicSharedMemorySize,
                         GEMM_SMEM);
    mma_gemm_kernel<1><<<dim3(C_/128, M_/128), 256, GEMM_SMEM>>>(out);
}

// round 17
// speedup vs baseline: 1.1338x; 1.0436x over previous
#include <cuda_runtime.h>
#include <cuda_bf16.h>
#include <math.h>
#include <stdint.h>

#define B_ 2
#define T_ 2048
#define C_ 768
#define H_ 12
#define D_ 64
#define M_ (B_*T_)       // 4096
#define NQKV_ (3*C_)     // 2304
#define KSLAB 32         // true-K per GEMM slab
#define NSLAB (C_/KSLAB) // 24

// ---------------------------------------------------------------------------
// Scratch (allocation-free rule: __device__ globals).
// Referenced ONLY from device code (host shadow-symbol bug, see R8).
// Split-bf16 operands stored as separate hi/lo arrays (no K-expansion).
// ---------------------------------------------------------------------------
__device__ __align__(256) __nv_bfloat16 g_qh[B_*H_*T_*D_], g_ql[B_*H_*T_*D_]; // [bh][t][d]
__device__ __align__(256) __nv_bfloat16 g_kh[B_*H_*T_*D_], g_kl[B_*H_*T_*D_]; // [bh][t][d]
__device__ __align__(256) __nv_bfloat16 g_vh[B_*H_*T_*D_], g_vl[B_*H_*T_*D_]; // [bh][d][t] (transposed!)
__device__ __align__(256) __nv_bfloat16 g_xh[M_*C_],  g_xl[M_*C_];        // x split [M][K]
__device__ __align__(256) __nv_bfloat16 g_ah[M_*C_],  g_al[M_*C_];        // attn out split [M][K]
__device__ __align__(256) __nv_bfloat16 g_wqh[NQKV_*C_], g_wql[NQKV_*C_]; // Wqkv^T split [N][K]
__device__ __align__(256) __nv_bfloat16 g_woh[C_*C_], g_wol[C_*C_];       // Wout^T split [N][K]

__device__ __forceinline__ uint32_t pack_bf(__nv_bfloat16 a, __nv_bfloat16 b) {
    return (uint32_t)__bfloat16_as_ushort(a) | ((uint32_t)__bfloat16_as_ushort(b) << 16);
}
__device__ __forceinline__ uint32_t smem_u32(const void* p) {
    uint32_t a;
    asm("{ .reg .u64 t; cvta.to.shared.u64 t, %1; cvt.u32.u64 %0, t; }" : "=r"(a) : "l"(p));
    return a;
}
__device__ __forceinline__ void cp16(uint32_t dst, const void* src) {
    asm volatile("cp.async.cg.shared.global [%0], [%1], 16;" :: "r"(dst), "l"(src));
}
#define CP_COMMIT() asm volatile("cp.async.commit_group;")
#define CP_WAIT(n)  asm volatile("cp.async.wait_group %0;" :: "n"(n))

#define MMA_BF16(acc, a, b0, b1) asm volatile( \
    "mma.sync.aligned.m16n8k16.row.col.f32.bf16.bf16.f32 " \
    "{%0,%1,%2,%3}, {%4,%5,%6,%7}, {%8,%9}, {%0,%1,%2,%3};" \
    : "+f"((acc)[0]), "+f"((acc)[1]), "+f"((acc)[2]), "+f"((acc)[3]) \
    : "r"((a)[0]), "r"((a)[1]), "r"((a)[2]), "r"((a)[3]), "r"(b0), "r"(b1))

#define LDMX4(r, addr) asm volatile( \
    "ldmatrix.sync.aligned.m8n8.x4.shared.b16 {%0,%1,%2,%3}, [%4];" \
    : "=r"((r)[0]), "=r"((r)[1]), "=r"((r)[2]), "=r"((r)[3]) : "r"(addr))

// ---------------------------------------------------------------------------
// Prep 1: x fp32 [M][C] -> g_xh / g_xl
// ---------------------------------------------------------------------------
__global__ void split_kernel(const float* __restrict__ src, int n4) {
    int i = blockIdx.x * blockDim.x + threadIdx.x;
    if (i >= n4) return;
    float4 v = ((const float4*)src)[i];
    float vv[4] = {v.x, v.y, v.z, v.w};
#pragma unroll
    for (int j = 0; j < 4; j++) {
        __nv_bfloat16 hi = __float2bfloat16(vv[j]);
        g_xh[i*4 + j] = hi;
        g_xl[i*4 + j] = __float2bfloat16(vv[j] - __bfloat162float(hi));
    }
}

// ---------------------------------------------------------------------------
// Prep 2: W fp32 [K][N] -> Wt hi/lo [N][K]
// ---------------------------------------------------------------------------
template<int WHICH>
__global__ void transpose_split_kernel(const float* __restrict__ W) {
    const int K = C_;
    const int N = (WHICH == 0) ? NQKV_ : C_;
    __nv_bfloat16* Th = (WHICH == 0) ? g_wqh : g_woh;
    __nv_bfloat16* Tl = (WHICH == 0) ? g_wql : g_wol;

    __shared__ float tile[32][33];
    const int c0 = blockIdx.x * 32;
    const int r0 = blockIdx.y * 32;
    const int tx = threadIdx.x, ty = threadIdx.y;
#pragma unroll
    for (int i = 0; i < 4; i++)
        tile[ty + i*8][tx] = W[(size_t)(r0 + ty + i*8) * N + c0 + tx];
    __syncthreads();
#pragma unroll
    for (int i = 0; i < 4; i++) {
        float v = tile[tx][ty + i*8];
        __nv_bfloat16 hi = __float2bfloat16(v);
        size_t o = (size_t)(c0 + ty + i*8) * K + r0 + tx;
        Th[o] = hi;
        Tl[o] = __float2bfloat16(v - __bfloat162float(hi));
    }
}

// ---------------------------------------------------------------------------
// HMMA GEMM, de-expanded: per k-slab (32 true K) load Ah/Al/Bh/Bl once and
// compute Ah*Bh + Ah*Bl + Al*Bh.  2-stage cp.async, one WAIT(0)+barrier per
// slab (R14-proven shape).  Pitch 80 (R12-proven conflict-free).
// smem: 2 stages x 4 tiles x 128x80 = 81920 B.
// MODE 0: A=g_xh/g_xl, B=g_wqh/g_wql -> scatter q/k/v split.
// MODE 1: A=g_ah/g_al, B=g_woh/g_wol -> outp fp32 [M][C].
// ---------------------------------------------------------------------------
#define GPITCH 80
#define GT_AL (128*GPITCH)       // 10240
#define GT_BH (2*128*GPITCH)     // 20480
#define GT_BL (3*128*GPITCH)     // 30720
#define G_STG (4*128*GPITCH)     // 40960
#define GEMM_SMEM (2*G_STG)      // 81920

template<int MODE>
__global__ __launch_bounds__(256) void mma_gemm_kernel(float* __restrict__ outp)
{
    const __nv_bfloat16* __restrict__ Ah = (MODE == 0) ? g_xh : g_ah;
    const __nv_bfloat16* __restrict__ Al = (MODE == 0) ? g_xl : g_al;
    const __nv_bfloat16* __restrict__ Bh = (MODE == 0) ? g_wqh : g_woh;
    const __nv_bfloat16* __restrict__ Bl = (MODE == 0) ? g_wql : g_wol;

    extern __shared__ unsigned char smem[];
    const uint32_t sbase = smem_u32(smem);

    const int tid = threadIdx.x;
    const int wid = tid >> 5, lane = tid & 31;
    const int gid = lane >> 2, tig = lane & 3;
    const int m0 = blockIdx.y << 7, n0 = blockIdx.x << 7;
    const int warp_m = wid & 1, warp_n = wid >> 1;

    float acc[4][4][4];
#pragma unroll
    for (int a = 0; a < 4; a++)
#pragma unroll
        for (int b = 0; b < 4; b++)
#pragma unroll
            for (int c = 0; c < 4; c++) acc[a][b][c] = 0.f;

    // per slab: each tile 128 rows x 4 chunks(16B); 512 chunks/tile, 2/thread
    auto issue = [&](int ks) {
        const uint32_t st = sbase + (uint32_t)(ks & 1) * G_STG;
        const size_t ko = (size_t)ks * KSLAB;
#pragma unroll
        for (int i = 0; i < 2; i++) {
            const int c = tid + i*256;
            const int row = c >> 2, q = c & 3;
            const uint32_t so = row*GPITCH + q*16;
            const size_t ga = (size_t)(m0 + row)*C_ + ko + q*8;
            const size_t gb = (size_t)(n0 + row)*C_ + ko + q*8;
            cp16(st +         so, Ah + ga);
            cp16(st + GT_AL + so, Al + ga);
            cp16(st + GT_BH + so, Bh + gb);
            cp16(st + GT_BL + so, Bl + gb);
        }
        CP_COMMIT();
    };

    issue(0);

    const int a_mrow = warp_m*64 + (lane & 7) + ((lane >> 3) & 1)*8;
    const uint32_t a_koff = (uint32_t)(lane >> 4) * 16;
    const int b_nrow = warp_n*32 + (lane & 7) + ((lane >> 4) & 1)*8;
    const uint32_t b_koff = (uint32_t)((lane >> 3) & 1) * 16;

    for (int ks = 0; ks < NSLAB; ks++) {
        CP_WAIT(0);
        __syncthreads();
        if (ks + 1 < NSLAB) issue(ks + 1);

        const uint32_t buf = sbase + (uint32_t)(ks & 1) * G_STG;

#pragma unroll
        for (int kst = 0; kst < 2; kst++) {
            const uint32_t ko = kst*32;
            // --- Ah, Bh: term Ah*Bh ---
            uint32_t af[4][4];
#pragma unroll
            for (int tm = 0; tm < 4; tm++)
                LDMX4(af[tm], buf + (a_mrow + tm*16)*GPITCH + ko + a_koff);
            uint32_t bhf[2][4];
#pragma unroll
            for (int tp = 0; tp < 2; tp++)
                LDMX4(bhf[tp], buf + GT_BH + (b_nrow + tp*16)*GPITCH + ko + b_koff);
#pragma unroll
            for (int tm = 0; tm < 4; tm++)
#pragma unroll
                for (int tn = 0; tn < 4; tn++)
                    MMA_BF16(acc[tm][tn], af[tm],
                             bhf[tn>>1][(tn&1)*2], bhf[tn>>1][(tn&1)*2 + 1]);
            // --- Bl: term Ah*Bl ---
            uint32_t blf[2][4];
#pragma unroll
            for (int tp = 0; tp < 2; tp++)
                LDMX4(blf[tp], buf + GT_BL + (b_nrow + tp*16)*GPITCH + ko + b_koff);
#pragma unroll
            for (int tm = 0; tm < 4; tm++)
#pragma unroll
                for (int tn = 0; tn < 4; tn++)
                    MMA_BF16(acc[tm][tn], af[tm],
                             blf[tn>>1][(tn&1)*2], blf[tn>>1][(tn&1)*2 + 1]);
            // --- Al (overwrites af): term Al*Bh ---
#pragma unroll
            for (int tm = 0; tm < 4; tm++)
                LDMX4(af[tm], buf + GT_AL + (a_mrow + tm*16)*GPITCH + ko + a_koff);
#pragma unroll
            for (int tm = 0; tm < 4; tm++)
#pragma unroll
                for (int tn = 0; tn < 4; tn++)
                    MMA_BF16(acc[tm][tn], af[tm],
                             bhf[tn>>1][(tn&1)*2], bhf[tn>>1][(tn&1)*2 + 1]);
        }
    }

    // ---- epilogue ----
#pragma unroll
    for (int tm = 0; tm < 4; tm++) {
        const int r0_ = m0 + warp_m*64 + tm*16 + gid;
#pragma unroll
        for (int tn = 0; tn < 4; tn++) {
            const int col = n0 + warp_n*32 + tn*8 + tig*2;
            if (MODE == 1) {
                float2 v0 = {acc[tm][tn][0], acc[tm][tn][1]};
                float2 v1 = {acc[tm][tn][2], acc[tm][tn][3]};
                *(float2*)&outp[(size_t)r0_ * C_ + col]       = v0;
                *(float2*)&outp[(size_t)(r0_ + 8) * C_ + col] = v1;
            } else {
                const int seg = n0 / C_;
                const int nrel = col - seg * C_;
                const int hh = nrel >> 6, dd = nrel & 63;
#pragma unroll
                for (int half = 0; half < 2; half++) {
                    const int m = r0_ + half * 8;
                    const int bb = m >> 11, tt = m & (T_ - 1);
                    const int bhh = bb*H_ + hh;
                    float v0 = acc[tm][tn][half*2], v1 = acc[tm][tn][half*2 + 1];
                    __nv_bfloat16 h0 = __float2bfloat16(v0);
                    __nv_bfloat16 h1 = __float2bfloat16(v1);
                    __nv_bfloat16 l0 = __float2bfloat16(v0 - __bfloat162float(h0));
                    __nv_bfloat16 l1 = __float2bfloat16(v1 - __bfloat162float(h1));
                    if (seg == 0) {
                        size_t base = ((size_t)bhh*T_ + tt)*D_ + dd;
                        *(uint32_t*)&g_qh[base] = pack_bf(h0, h1);
                        *(uint32_t*)&g_ql[base] = pack_bf(l0, l1);
                    } else if (seg == 1) {
                        size_t base = ((size_t)bhh*T_ + tt)*D_ + dd;
                        *(uint32_t*)&g_kh[base] = pack_bf(h0, h1);
                        *(uint32_t*)&g_kl[base] = pack_bf(l0, l1);
                    } else {
                        size_t base = ((size_t)bhh*D_ + dd)*T_ + tt;  // d-major
                        g_vh[base]      = h0;  g_vl[base]      = l0;
                        g_vh[base + T_] = h1;  g_vl[base + T_] = l1;
                    }
                }
            }
        }
    }
}

// ---------------------------------------------------------------------------
// HMMA causal flash attention (R16, passed): Q tile 128 rows, 8 warps,
// 2-stage cp.async K/V, one barrier per k-tile, ldmatrix fragments.
// Epilogue now writes split hi/lo into g_ah/g_al (plain [M][C]).
// ---------------------------------------------------------------------------
#define APITCH 144
#define AQ_LO  (128*APITCH)        // 18432
#define AKV_OFF (2*128*APITCH)     // 36864
#define AKV_STG 36864
#define ATTN_SMEM (AKV_OFF + 2*AKV_STG)   // 110592

__global__ __launch_bounds__(256) void attn_mma_kernel() {
    extern __shared__ unsigned char smem[];
    const uint32_t sbase = smem_u32(smem);
    const int tid = threadIdx.x;
    const int wid = tid >> 5, lane = tid & 31;
    const int gid = lane >> 2, tig = lane & 3;
    const int bh = blockIdx.y;
    const int b = bh / H_, h = bh % H_;
    const int qt = (int)(gridDim.x - 1) - (int)blockIdx.x;   // heavy first
    const int ktmax = 2*qt + 1;

    const size_t qkbase = (size_t)bh * T_ * D_;
    const size_t vbase  = (size_t)bh * D_ * T_;

    auto issue_kv = [&](int kt2) {
        const uint32_t st = sbase + AKV_OFF + (uint32_t)(kt2 & 1) * AKV_STG;
#pragma unroll
        for (int i = 0; i < 2; i++) {
            const int c = tid + i*256;
            const int row = c >> 3, q = c & 7;
            const size_t gk = qkbase + (size_t)(kt2*64 + row)*D_ + q*8;
            const size_t gv = vbase + (size_t)row*T_ + kt2*64 + q*8;
            cp16(st +         row*APITCH + q*16, g_kh + gk);
            cp16(st + 9216  + row*APITCH + q*16, g_kl + gk);
            cp16(st + 18432 + row*APITCH + q*16, g_vh + gv);
            cp16(st + 27648 + row*APITCH + q*16, g_vl + gv);
        }
        CP_COMMIT();
    };

#pragma unroll
    for (int i = 0; i < 4; i++) {
        const int c = tid + i*256;
        const int row = c >> 3, q = c & 7;
        const size_t g = qkbase + (size_t)(qt*128 + row)*D_ + q*8;
        *(uint4*)(smem + row*APITCH + q*16)         = *(const uint4*)(g_qh + g);
        *(uint4*)(smem + AQ_LO + row*APITCH + q*16) = *(const uint4*)(g_ql + g);
    }

    issue_kv(0);

    float m0 = -1e30f, m1 = -1e30f, l0 = 0.f, l1 = 0.f;
    float o[8][4];
#pragma unroll
    for (int d = 0; d < 8; d++)
#pragma unroll
        for (int c = 0; c < 4; c++) o[d][c] = 0.f;

    const int arow = wid*16 + gid;
    const int grow0 = qt*128 + arow;

    const int a_row  = wid*16 + (lane & 7) + ((lane >> 3) & 1)*8;
    const uint32_t a_koff = (uint32_t)(lane >> 4) * 16;
    const int b_row  = (lane & 7) + ((lane >> 4) & 1)*8;
    const uint32_t b_koff = (uint32_t)((lane >> 3) & 1) * 16;

    for (int kt = 0; kt <= ktmax; kt++) {
        CP_WAIT(0);
        __syncthreads();
        if (kt + 1 <= ktmax) issue_kv(kt + 1);

        const uint32_t kv = sbase + AKV_OFF + (uint32_t)(kt & 1) * AKV_STG;
        const uint32_t KH = kv;
        const uint32_t KL = kv + 9216;
        const uint32_t VH = kv + 18432;
        const uint32_t VL = kv + 27648;

        float s[8][4];
#pragma unroll
        for (int nb = 0; nb < 8; nb++)
#pragma unroll
            for (int c = 0; c < 4; c++) s[nb][c] = 0.f;

#pragma unroll
        for (int kc = 0; kc < 4; kc++) {
            uint32_t ah[4], al[4];
            LDMX4(ah, sbase + a_row*APITCH + kc*32 + a_koff);
            LDMX4(al, sbase + AQ_LO + a_row*APITCH + kc*32 + a_koff);
#pragma unroll
            for (int tp = 0; tp < 4; tp++) {
                uint32_t kh[4], kl[4];
                LDMX4(kh, KH + (tp*16 + b_row)*APITCH + kc*32 + b_koff);
                LDMX4(kl, KL + (tp*16 + b_row)*APITCH + kc*32 + b_koff);
                MMA_BF16(s[2*tp],   ah, kh[0], kh[1]);
                MMA_BF16(s[2*tp],   ah, kl[0], kl[1]);
                MMA_BF16(s[2*tp],   al, kh[0], kh[1]);
                MMA_BF16(s[2*tp+1], ah, kh[2], kh[3]);
                MMA_BF16(s[2*tp+1], ah, kl[2], kl[3]);
                MMA_BF16(s[2*tp+1], al, kh[2], kh[3]);
            }
        }

        const float scale = 0.125f;
        if (kt >= 2*qt) {
#pragma unroll
            for (int nb = 0; nb < 8; nb++) {
                const int colb = kt*64 + nb*8 + tig*2;
                s[nb][0] = (colb     <= grow0    ) ? s[nb][0]*scale : -1e30f;
                s[nb][1] = (colb + 1 <= grow0    ) ? s[nb][1]*scale : -1e30f;
                s[nb][2] = (colb     <= grow0 + 8) ? s[nb][2]*scale : -1e30f;
                s[nb][3] = (colb + 1 <= grow0 + 8) ? s[nb][3]*scale : -1e30f;
            }
        } else {
#pragma unroll
            for (int nb = 0; nb < 8; nb++)
#pragma unroll
                for (int c = 0; c < 4; c++) s[nb][c] *= scale;
        }

        float mx0 = -1e30f, mx1 = -1e30f;
#pragma unroll
        for (int nb = 0; nb < 8; nb++) {
            mx0 = fmaxf(mx0, fmaxf(s[nb][0], s[nb][1]));
            mx1 = fmaxf(mx1, fmaxf(s[nb][2], s[nb][3]));
        }
#pragma unroll
        for (int off = 1; off <= 2; off <<= 1) {
            mx0 = fmaxf(mx0, __shfl_xor_sync(0xffffffffu, mx0, off));
            mx1 = fmaxf(mx1, __shfl_xor_sync(0xffffffffu, mx1, off));
        }
        const float mn0 = fmaxf(m0, mx0), mn1 = fmaxf(m1, mx1);
        const float cr0 = __expf(m0 - mn0), cr1 = __expf(m1 - mn1);
        float sum0 = 0.f, sum1 = 0.f;
#pragma unroll
        for (int nb = 0; nb < 8; nb++) {
            s[nb][0] = __expf(s[nb][0] - mn0);
            s[nb][1] = __expf(s[nb][1] - mn0);
            s[nb][2] = __expf(s[nb][2] - mn1);
            s[nb][3] = __expf(s[nb][3] - mn1);
            sum0 += s[nb][0] + s[nb][1];
            sum1 += s[nb][2] + s[nb][3];
        }
#pragma unroll
        for (int off = 1; off <= 2; off <<= 1) {
            sum0 += __shfl_xor_sync(0xffffffffu, sum0, off);
            sum1 += __shfl_xor_sync(0xffffffffu, sum1, off);
        }
        l0 = l0 * cr0 + sum0;  m0 = mn0;
        l1 = l1 * cr1 + sum1;  m1 = mn1;
#pragma unroll
        for (int db = 0; db < 8; db++) {
            o[db][0] *= cr0; o[db][1] *= cr0;
            o[db][2] *= cr1; o[db][3] *= cr1;
        }

        uint32_t ph[4][4], pl[4][4];
#pragma unroll
        for (int kc = 0; kc < 4; kc++) {
#pragma unroll
            for (int part = 0; part < 2; part++) {
                const int nb = 2*kc + part;
                __nv_bfloat16 h0 = __float2bfloat16(s[nb][0]);
                __nv_bfloat16 h1 = __float2bfloat16(s[nb][1]);
                __nv_bfloat16 h2 = __float2bfloat16(s[nb][2]);
                __nv_bfloat16 h3 = __float2bfloat16(s[nb][3]);
                ph[kc][0 + part*2] = pack_bf(h0, h1);
                ph[kc][1 + part*2] = pack_bf(h2, h3);
                pl[kc][0 + part*2] = pack_bf(
                    __float2bfloat16(s[nb][0] - __bfloat162float(h0)),
                    __float2bfloat16(s[nb][1] - __bfloat162float(h1)));
                pl[kc][1 + part*2] = pack_bf(
                    __float2bfloat16(s[nb][2] - __bfloat162float(h2)),
                    __float2bfloat16(s[nb][3] - __bfloat162float(h3)));
            }
        }

#pragma unroll
        for (int kc = 0; kc < 4; kc++) {
#pragma unroll
            for (int tp = 0; tp < 4; tp++) {
                uint32_t vh[4], vl[4];
                LDMX4(vh, VH + (tp*16 + b_row)*APITCH + kc*32 + b_koff);
                LDMX4(vl, VL + (tp*16 + b_row)*APITCH + kc*32 + b_koff);
                MMA_BF16(o[2*tp],   ph[kc], vh[0], vh[1]);
                MMA_BF16(o[2*tp],   ph[kc], vl[0], vl[1]);
                MMA_BF16(o[2*tp],   pl[kc], vh[0], vh[1]);
                MMA_BF16(o[2*tp+1], ph[kc], vh[2], vh[3]);
                MMA_BF16(o[2*tp+1], ph[kc], vl[2], vl[3]);
                MMA_BF16(o[2*tp+1], pl[kc], vh[2], vh[3]);
            }
        }
    }

    // ---- epilogue: write split hi/lo [M][C] ----
    const float i0 = 1.f / l0, i1 = 1.f / l1;
    const int gr = b*T_ + grow0;
#pragma unroll
    for (int db = 0; db < 8; db++) {
#pragma unroll
        for (int c = 0; c < 4; c++) {
            const float val = o[db][c] * ((c < 2) ? i0 : i1);
            const int row = (c < 2) ? gr : gr + 8;
            const int col = h*64 + db*8 + tig*2 + (c & 1);
            const size_t base = (size_t)row * C_ + col;
            __nv_bfloat16 hi = __float2bfloat16(val);
            g_ah[base] = hi;
            g_al[base] = __float2bfloat16(val - __bfloat162float(hi));
        }
    }
}

// ---------------------------------------------------------------------------
extern "C" void kernel_launch(void* const* d_in, const int* in_sizes, int n_in,
                              void* d_out, int out_size) {
    const float* x    = (const float*)d_in[0];
    const float* Wqkv = (const float*)d_in[1];
    const float* Wout = (const float*)d_in[2];
    float* out = (float*)d_out;

    split_kernel<<<(M_*C_/4 + 255)/256, 256>>>(x, M_*C_/4);
    transpose_split_kernel<0><<<dim3(NQKV_/32, C_/32), dim3(32, 8)>>>(Wqkv);
    transpose_split_kernel<1><<<dim3(C_/32, C_/32), dim3(32, 8)>>>(Wout);

    // QKV projection (HMMA, de-expanded 3-term, 2-stage)
    cudaFuncSetAttribute(mma_gemm_kernel<0>, cudaFuncAttributeMaxDynamicSharedMemorySize,
                         GEMM_SMEM);
    mma_gemm_kernel<0><<<dim3(NQKV_/128, M_/128), 256, GEMM_SMEM>>>(nullptr);

    // Flash attention on tensor cores
    cudaFuncSetAttribute(attn_mma_kernel, cudaFuncAttributeMaxDynamicSharedMemorySize,
                         ATTN_SMEM);
    attn_mma_kernel<<<dim3(T_/128, B_*H_), 256, ATTN_SMEM>>>();

    // Output projection (HMMA)
    cudaFuncSetAttribute(mma_gemm_kernel<1>, cudaFuncAttributeMaxDynamicSharedMemorySize,
                         GEMM_SMEM);
    mma_gemm_kernel<1><<<dim3(C_/128, M_/128), 256, GEMM_SMEM>>>(out);
}